// round 12
// baseline (speedup 1.0000x reference)
#include <cuda_runtime.h>
#include <math.h>
#include <stdint.h>

// Problem constants
#define B_   4
#define N_   2048
#define M_   256
#define DIM_ 1024
#define HEADS_ 16
#define HD_  64
#define QSCALE_ 0.125f   // 64^-0.5
#define NEGMAX_ -3.4028235e38f

// ---------------- scratch (device globals; no allocation allowed) ----------
__device__ float g_xn[(size_t)B_*N_*DIM_];          // LN(x), tf32-rounded
__device__ float g_ln[(size_t)2*B_*M_*DIM_];        // LN(latents), tf32-rounded
__device__ float g_kv[(size_t)B_*N_*2*DIM_];        // kv = xn@Wkv (fp32, raw)
__device__ float g_q [(size_t)2*B_*M_*DIM_];        // q raw (rmsnorm in attn)
__device__ float g_o [(size_t)2*B_*M_*DIM_];        // attn out, tf32-rounded
__device__ float g_wp[(size_t)4*1024*1024];         // fragment-packed tf32 weights

// ---------------- helpers ---------------------------------------------------
__device__ __forceinline__ uint32_t f2tf32(float f) {
    uint32_t r;
    asm("cvt.rna.tf32.f32 %0, %1;" : "=r"(r) : "f"(f));
    return r;
}
__device__ __forceinline__ float tf32r(float f) { return __uint_as_float(f2tf32(f)); }

__device__ __forceinline__ uint32_t smem_u32(const void* p) {
    uint32_t a;
    asm("{ .reg .u64 t; cvta.to.shared.u64 t, %1; cvt.u32.u64 %0, t; }"
        : "=r"(a) : "l"(p));
    return a;
}
__device__ __forceinline__ void cp16(uint32_t dst, const void* src) {
    asm volatile("cp.async.cg.shared.global [%0], [%1], 16;" :: "r"(dst), "l"(src));
}
#define CP_COMMIT() asm volatile("cp.async.commit_group;" ::: "memory")
#define CP_WAIT(n)  asm volatile("cp.async.wait_group %0;" :: "n"(n) : "memory")

__device__ __forceinline__ void mma_tf32(float* d, uint32_t a0, uint32_t a1,
                                         uint32_t a2, uint32_t a3,
                                         uint32_t b0, uint32_t b1) {
    asm volatile(
        "mma.sync.aligned.m16n8k8.row.col.f32.tf32.tf32.f32 "
        "{%0,%1,%2,%3}, {%4,%5,%6,%7}, {%8,%9}, {%0,%1,%2,%3};"
        : "+f"(d[0]), "+f"(d[1]), "+f"(d[2]), "+f"(d[3])
        : "r"(a0), "r"(a1), "r"(a2), "r"(a3), "r"(b0), "r"(b1));
}

// ---------------- LayerNorm body --------------------------------------------
__device__ __forceinline__ void ln_body(const float* __restrict__ in,
                                        float* __restrict__ out,
                                        const float* __restrict__ w,
                                        const float* __restrict__ bb,
                                        int row, int t,
                                        float* red1, float* red2) {
    const float4 v = ((const float4*)(in + (size_t)row * 1024))[t];
    float s  = v.x + v.y + v.z + v.w;
    float ss = v.x*v.x + v.y*v.y + v.z*v.z + v.w*v.w;
    #pragma unroll
    for (int o = 16; o > 0; o >>= 1) {
        s  += __shfl_xor_sync(0xffffffffu, s, o);
        ss += __shfl_xor_sync(0xffffffffu, ss, o);
    }
    if ((t & 31) == 0) { red1[t >> 5] = s; red2[t >> 5] = ss; }
    __syncthreads();
    s  = red1[0]+red1[1]+red1[2]+red1[3]+red1[4]+red1[5]+red1[6]+red1[7];
    ss = red2[0]+red2[1]+red2[2]+red2[3]+red2[4]+red2[5]+red2[6]+red2[7];
    const float mu  = s * (1.0f/1024.0f);
    const float var = ss * (1.0f/1024.0f) - mu*mu;
    const float inv = rsqrtf(var + 1e-5f);
    const float4 wv = ((const float4*)w)[t];
    const float4 bv = ((const float4*)bb)[t];
    float4 r;
    r.x = tf32r((v.x - mu) * inv * wv.x + bv.x);
    r.y = tf32r((v.y - mu) * inv * wv.y + bv.y);
    r.z = tf32r((v.z - mu) * inv * wv.z + bv.z);
    r.w = tf32r((v.w - mu) * inv * wv.w + bv.w);
    ((float4*)(out + (size_t)row * 1024))[t] = r;
}

__global__ __launch_bounds__(256) void ln_kernel(const float* __restrict__ in,
                                                 float* __restrict__ out,
                                                 const float* __restrict__ w,
                                                 const float* __restrict__ bb) {
    __shared__ float red1[8], red2[8];
    ln_body(in, out, w, bb, blockIdx.x, threadIdx.x, red1, red2);
}

__global__ __launch_bounds__(256) void ln_lat_kernel(const float* __restrict__ in0,
                                                     const float* __restrict__ in1,
                                                     float* __restrict__ out,
                                                     const float* __restrict__ w,
                                                     const float* __restrict__ bb) {
    __shared__ float red1[8], red2[8];
    const float* in = blockIdx.y ? in1 : in0;
    float* o = out + (size_t)blockIdx.y * B_ * M_ * DIM_;
    ln_body(in, o, w, bb, blockIdx.x, threadIdx.x, red1, red2);
}

// ---------------- merged weight pack (3 weights, blockIdx.z selects) --------
__global__ __launch_bounds__(256) void pack_all(const float* __restrict__ Wkv,
                                                const float* __restrict__ Wq,
                                                const float* __restrict__ Wout,
                                                float* __restrict__ wp) {
    const int z = blockIdx.z;
    if (z > 0 && blockIdx.x >= 8) return;
    const float* W = (z == 0) ? Wkv : (z == 1 ? Wq : Wout);
    const int Nfull = (z == 0) ? 2048 : 1024;
    float* out = wp + (z == 0 ? 0 : (z == 1 ? (size_t)2*1024*1024 : (size_t)3*1024*1024));
    const int Kdim = 1024;

    const int nblk = blockIdx.x, kc = blockIdx.y;
    const int kin = threadIdx.x >> 3;
    const int k = kc * 32 + kin;
    const int n0 = (threadIdx.x & 7) * 16;
    float* tout = out + ((size_t)nblk * (Kdim >> 5) + kc) * 4096;
    const float* src = W + (size_t)k * Nfull + nblk * 128 + n0;
    const int sp = kin >> 4;
    const int pos = ((kin >> 3) & 1) * 2 + ((kin >> 2) & 1);
    const int klo = kin & 3;
    #pragma unroll
    for (int i = 0; i < 16; i += 4) {
        const float4 v = *(const float4*)(src + i);
        const float vv[4] = {v.x, v.y, v.z, v.w};
        #pragma unroll
        for (int e = 0; e < 4; e++) {
            const int nloc = n0 + i + e;
            const int nn = nloc >> 3;
            const int lane = (nloc & 7) * 4 + klo;
            tout[((nn*2 + sp)*32 + lane)*4 + pos] = __uint_as_float(f2tf32(vv[e]));
        }
    }
}

// ------- 3-stage cp.async GEMM body: CTA 128x128, warp 32x64, K-chunk 32 -----
#define GEMM_SMEM (3 * 32768)
__device__ __forceinline__ void gemm_body(const float* __restrict__ A,
                                          const float* __restrict__ Bpk,
                                          float* __restrict__ C,
                                          const float* __restrict__ bias,
                                          int Ntot, int Kdim,
                                          int brow, int bxi, float* gsm) {
    const uint32_t smb = smem_u32(gsm);
    const int tid = threadIdx.x;
    const int lane = tid & 31;
    const int wid = tid >> 5;
    const int wr = wid >> 1, wc = wid & 1;
    const int bcol = bxi * 128;

    const int arow = tid >> 1;
    const int aseg0 = (tid & 1) * 4;
    const float* Agb = A + (size_t)(brow + arow) * Kdim + aseg0 * 4;
    uint32_t adst[4];
    #pragma unroll
    for (int i = 0; i < 4; i++) {
        const int seg = aseg0 + i;
        adst[i] = smb + (uint32_t)((arow * 8 + (seg ^ (arow & 7))) * 16);
    }
    const float* Bgb = Bpk + (size_t)bxi * (Kdim >> 5) * 4096 + tid * 16;
    const uint32_t bdst = smb + 49152u + (uint32_t)(tid * 64);

    float d[2][8][4];
    #pragma unroll
    for (int f = 0; f < 2; f++)
        #pragma unroll
        for (int nf = 0; nf < 8; nf++)
            #pragma unroll
            for (int r = 0; r < 4; r++) d[f][nf][r] = 0.0f;

    const int NK = Kdim >> 5;

    #pragma unroll
    for (int s = 0; s < 2; s++) {
        const float* Ag = Agb + s * 32;
        const float* Bg = Bgb + (size_t)s * 4096;
        #pragma unroll
        for (int i = 0; i < 4; i++) cp16(adst[i] + s * 16384u, Ag + i * 4);
        #pragma unroll
        for (int i = 0; i < 4; i++) cp16(bdst + s * 16384u + i * 16, Bg + i * 4);
        CP_COMMIT();
    }

    for (int kc = 0; kc < NK; kc++) {
        const int buf = kc % 3;
        CP_WAIT(1);
        __syncthreads();
        if (kc + 2 < NK) {
            const int nb = (kc + 2) % 3;
            const float* Ag = Agb + (kc + 2) * 32;
            const float* Bg = Bgb + (size_t)(kc + 2) * 4096;
            #pragma unroll
            for (int i = 0; i < 4; i++) cp16(adst[i] + nb * 16384u, Ag + i * 4);
            #pragma unroll
            for (int i = 0; i < 4; i++) cp16(bdst + nb * 16384u + i * 16, Bg + i * 4);
        }
        CP_COMMIT();

        const float* As = gsm + buf * 4096;
        const uint4* Bs4 = (const uint4*)(gsm + 12288 + buf * 4096);
        #pragma unroll
        for (int sp = 0; sp < 2; sp++) {
            uint32_t af[2][2][4];
            #pragma unroll
            for (int f = 0; f < 2; f++) {
                const int r0 = wr*32 + f*16 + (lane >> 2);
                const int r1 = r0 + 8;
                const int sw = (r0 & 7) << 2;
                #pragma unroll
                for (int s2 = 0; s2 < 2; s2++) {
                    const int c = (2*sp + s2)*8 + (lane & 3);
                    af[f][s2][0] = __float_as_uint(As[r0*32 + (c ^ sw)]);
                    af[f][s2][1] = __float_as_uint(As[r1*32 + (c ^ sw)]);
                    af[f][s2][2] = __float_as_uint(As[r0*32 + ((c+4) ^ sw)]);
                    af[f][s2][3] = __float_as_uint(As[r1*32 + ((c+4) ^ sw)]);
                }
            }
            #pragma unroll
            for (int nf = 0; nf < 8; nf++) {
                const uint4 bb = Bs4[((wc*8 + nf)*2 + sp)*32 + lane];
                mma_tf32(d[0][nf], af[0][0][0], af[0][0][1], af[0][0][2], af[0][0][3], bb.x, bb.y);
                mma_tf32(d[1][nf], af[1][0][0], af[1][0][1], af[1][0][2], af[1][0][3], bb.x, bb.y);
                mma_tf32(d[0][nf], af[0][1][0], af[0][1][1], af[0][1][2], af[0][1][3], bb.z, bb.w);
                mma_tf32(d[1][nf], af[1][1][0], af[1][1][1], af[1][1][2], af[1][1][3], bb.z, bb.w);
            }
        }
    }

    const int g = lane >> 2, cq = lane & 3;
    #pragma unroll
    for (int f = 0; f < 2; f++) {
        #pragma unroll
        for (int nf = 0; nf < 8; nf++) {
            const int row0 = brow + wr*32 + f*16 + g;
            const int col  = bcol + wc*64 + nf*8 + cq*2;
            float b0 = 0.0f, b1 = 0.0f;
            if (bias) { b0 = bias[col]; b1 = bias[col + 1]; }
            *(float2*)&C[(size_t)row0 * Ntot + col] =
                make_float2(d[f][nf][0] + b0, d[f][nf][1] + b1);
            *(float2*)&C[(size_t)(row0 + 8) * Ntot + col] =
                make_float2(d[f][nf][2] + b0, d[f][nf][3] + b1);
        }
    }
}

__global__ __launch_bounds__(256, 2) void gemm_cp(const float* __restrict__ A,
                                                  const float* __restrict__ Bpk,
                                                  float* __restrict__ C,
                                                  const float* __restrict__ bias,
                                                  int Ntot, int Kdim) {
    extern __shared__ float gsm[];
    gemm_body(A, Bpk, C, bias, Ntot, Kdim, blockIdx.y * 128, blockIdx.x, gsm);
}

// fused kv (y<64) + q (y in [64,80), x<8) GEMM
__global__ __launch_bounds__(256, 2) void gemm_fused(const float* __restrict__ A0,
                                                     const float* __restrict__ B0,
                                                     float* __restrict__ C0,
                                                     const float* __restrict__ A1,
                                                     const float* __restrict__ B1,
                                                     float* __restrict__ C1) {
    extern __shared__ float gsm[];
    if (blockIdx.y < 64) {
        gemm_body(A0, B0, C0, nullptr, 2048, 1024, blockIdx.y * 128, blockIdx.x, gsm);
    } else {
        if (blockIdx.x >= 8) return;
        gemm_body(A1, B1, C1, nullptr, 1024, 1024, (blockIdx.y - 64) * 128, blockIdx.x, gsm);
    }
}

// ---------------- flash attention, fused rmsnorms, K/V register prefetch -----
#define QS_OFF 0
#define KS_OFF 8704
#define VS_OFF 13056
#define PS_OFF 17664
#define ATTN_SMEM (26368*4 + 2048)
__global__ __launch_bounds__(256, 2) void attn_kernel(const float* __restrict__ q,
                                                      const float* __restrict__ kv,
                                                      const int* __restrict__ mask,
                                                      const float* __restrict__ gamma_q,
                                                      const float* __restrict__ gamma_k,
                                                      float* __restrict__ o) {
    extern __shared__ float sm[];
    float* Qs = sm + QS_OFF;
    float* Ks = sm + KS_OFF;
    float* Vs = sm + VS_OFF;
    float* Ps = sm + PS_OFF;
    unsigned char* msk = (unsigned char*)(sm + 26368);

    const int qt = blockIdx.x;
    const int h  = blockIdx.y;
    const int s  = blockIdx.z >> 2;
    const int b  = blockIdx.z & 3;
    const int tid = threadIdx.x;
    const int lane = tid & 31;
    const int wid = tid >> 5;
    const int gid = lane >> 2, tig = lane & 3;
    const int wr = wid * 16;
    const int rA = wr + gid, rB = rA + 8;

    // ---- load Q tile: rmsnorm * QSCALE * (gamma_q*gamma_k) folded ----
    {
        const int row = tid >> 1;
        const int cl = (tid & 1) * 32;
        const float* qp = q + ((size_t)((s*4 + b)*256 + qt*128 + row)) * 1024 + h*64 + cl;
        float4 qv[8];
        float ssq = 0.0f;
        #pragma unroll
        for (int i = 0; i < 8; i++) {
            qv[i] = ((const float4*)qp)[i];
            ssq += qv[i].x*qv[i].x + qv[i].y*qv[i].y + qv[i].z*qv[i].z + qv[i].w*qv[i].w;
        }
        ssq += __shfl_xor_sync(0xffffffffu, ssq, 1);
        const float inv = QSCALE_ / fmaxf(sqrtf(ssq * (1.0f/64.0f)), 1e-8f);
        #pragma unroll
        for (int i = 0; i < 8; i++) {
            const float4 g1 = ((const float4*)(gamma_q + cl))[i];
            const float4 g2 = ((const float4*)(gamma_k + cl))[i];
            *(float4*)&Qs[row*68 + cl + i*4] =
                make_float4(tf32r(qv[i].x * inv * g1.x * g2.x),
                            tf32r(qv[i].y * inv * g1.y * g2.y),
                            tf32r(qv[i].z * inv * g1.z * g2.z),
                            tf32r(qv[i].w * inv * g1.w * g2.w));
        }
        const int4* mi = (const int4*)(mask + (size_t)b * 2048);
        #pragma unroll
        for (int i = 0; i < 2; i++) {
            const int4 mv = mi[tid * 2 + i];
            const int base = tid * 8 + i * 4;
            msk[base + 0] = (unsigned char)(mv.x != 0);
            msk[base + 1] = (unsigned char)(mv.y != 0);
            msk[base + 2] = (unsigned char)(mv.z != 0);
            msk[base + 3] = (unsigned char)(mv.w != 0);
        }
    }

    float mA = -INFINITY, mB = -INFINITY, lA = 0.0f, lB = 0.0f;
    float oa[8][4];
    #pragma unroll
    for (int n = 0; n < 8; n++)
        #pragma unroll
        for (int r = 0; r < 4; r++) oa[n][r] = 0.0f;

    const float* kbase = kv + (size_t)b * 2048 * 2048 + h * 64;
    const int key = tid >> 2;
    const int cb = (tid & 3) * 16;

    // prologue: prefetch chunk 0 K/V into registers
    float4 kq[4], vv[4];
    {
        const float* kp = kbase + (size_t)key * 2048 + cb;
        #pragma unroll
        for (int i = 0; i < 4; i++) {
            kq[i] = ((const float4*)kp)[i];
            vv[i] = ((const float4*)(kp + 1024))[i];
        }
    }

    for (int c0 = 0; c0 < 2048; c0 += 64) {
        // ---- write phase: rmsnorm K regs, tf32 V regs -> smem ----
        {
            float ssq = 0.0f;
            #pragma unroll
            for (int i = 0; i < 4; i++)
                ssq += kq[i].x*kq[i].x + kq[i].y*kq[i].y + kq[i].z*kq[i].z + kq[i].w*kq[i].w;
            ssq += __shfl_xor_sync(0xffffffffu, ssq, 1);
            ssq += __shfl_xor_sync(0xffffffffu, ssq, 2);
            const float inv = 1.0f / fmaxf(sqrtf(ssq * (1.0f/64.0f)), 1e-8f);
            #pragma unroll
            for (int i = 0; i < 4; i++) {
                *(float4*)&Ks[key*68 + cb + i*4] =
                    make_float4(tf32r(kq[i].x * inv), tf32r(kq[i].y * inv),
                                tf32r(kq[i].z * inv), tf32r(kq[i].w * inv));
                *(float4*)&Vs[key*72 + cb + i*4] =
                    make_float4(tf32r(vv[i].x), tf32r(vv[i].y),
                                tf32r(vv[i].z), tf32r(vv[i].w));
            }
        }
        __syncthreads();

        // ---- prefetch next chunk (latency hidden behind compute) ----
        if (c0 + 64 < 2048) {
            const float* kp = kbase + (size_t)(c0 + 64 + key) * 2048 + cb;
            #pragma unroll
            for (int i = 0; i < 4; i++) {
                kq[i] = ((const float4*)kp)[i];
                vv[i] = ((const float4*)(kp + 1024))[i];
            }
        }

        // ---- S = Q K^T ----
        float sc[8][4];
        #pragma unroll
        for (int n = 0; n < 8; n++)
            #pragma unroll
            for (int r = 0; r < 4; r++) sc[n][r] = 0.0f;
        #pragma unroll
        for (int kh = 0; kh < 2; kh++) {
            uint32_t af[4][4];
            #pragma unroll
            for (int k4 = 0; k4 < 4; k4++) {
                const int base = (kh*4 + k4)*8 + tig;
                af[k4][0] = __float_as_uint(Qs[rA*68 + base]);
                af[k4][1] = __float_as_uint(Qs[rB*68 + base]);
                af[k4][2] = __float_as_uint(Qs[rA*68 + base + 4]);
                af[k4][3] = __float_as_uint(Qs[rB*68 + base + 4]);
            }
            #pragma unroll
            for (int n = 0; n < 8; n++) {
                #pragma unroll
                for (int k4 = 0; k4 < 4; k4++) {
                    const int base = (kh*4 + k4)*8 + tig;
                    const uint32_t b0 = __float_as_uint(Ks[(n*8 + gid)*68 + base]);
                    const uint32_t b1 = __float_as_uint(Ks[(n*8 + gid)*68 + base + 4]);
                    mma_tf32(sc[n], af[k4][0], af[k4][1], af[k4][2], af[k4][3], b0, b1);
                }
            }
        }

        if (s == 0) {
            #pragma unroll
            for (int n = 0; n < 8; n++) {
                const int kl = c0 + n*8 + 2*tig;
                if (!msk[kl])   { sc[n][0] = NEGMAX_; sc[n][2] = NEGMAX_; }
                if (!msk[kl+1]) { sc[n][1] = NEGMAX_; sc[n][3] = NEGMAX_; }
            }
        }

        float cmA = -INFINITY, cmB = -INFINITY;
        #pragma unroll
        for (int n = 0; n < 8; n++) {
            cmA = fmaxf(cmA, fmaxf(sc[n][0], sc[n][1]));
            cmB = fmaxf(cmB, fmaxf(sc[n][2], sc[n][3]));
        }
        cmA = fmaxf(cmA, __shfl_xor_sync(0xffffffffu, cmA, 1));
        cmA = fmaxf(cmA, __shfl_xor_sync(0xffffffffu, cmA, 2));
        cmB = fmaxf(cmB, __shfl_xor_sync(0xffffffffu, cmB, 1));
        cmB = fmaxf(cmB, __shfl_xor_sync(0xffffffffu, cmB, 2));
        const float nmA = fmaxf(mA, cmA), nmB = fmaxf(mB, cmB);
        const float scaA = __expf(mA - nmA), scaB = __expf(mB - nmB);
        float rsA = 0.0f, rsB = 0.0f;
        #pragma unroll
        for (int n = 0; n < 8; n++) {
            const float p0 = __expf(sc[n][0] - nmA);
            const float p1 = __expf(sc[n][1] - nmA);
            const float p2 = __expf(sc[n][2] - nmB);
            const float p3 = __expf(sc[n][3] - nmB);
            rsA += p0 + p1; rsB += p2 + p3;
            sc[n][0] = p0; sc[n][1] = p1; sc[n][2] = p2; sc[n][3] = p3;
        }
        rsA += __shfl_xor_sync(0xffffffffu, rsA, 1);
        rsA += __shfl_xor_sync(0xffffffffu, rsA, 2);
        rsB += __shfl_xor_sync(0xffffffffu, rsB, 1);
        rsB += __shfl_xor_sync(0xffffffffu, rsB, 2);
        lA = lA * scaA + rsA; mA = nmA;
        lB = lB * scaB + rsB; mB = nmB;
        #pragma unroll
        for (int n = 0; n < 8; n++) {
            oa[n][0] *= scaA; oa[n][1] *= scaA;
            oa[n][2] *= scaB; oa[n][3] *= scaB;
            *(float2*)&Ps[rA*68 + n*8 + 2*tig] = make_float2(tf32r(sc[n][0]), tf32r(sc[n][1]));
            *(float2*)&Ps[rB*68 + n*8 + 2*tig] = make_float2(tf32r(sc[n][2]), tf32r(sc[n][3]));
        }
        __syncwarp();

        #pragma unroll
        for (int kh = 0; kh < 2; kh++) {
            uint32_t pf[4][4];
            #pragma unroll
            for (int k4 = 0; k4 < 4; k4++) {
                const int base = (kh*4 + k4)*8 + tig;
                pf[k4][0] = __float_as_uint(Ps[rA*68 + base]);
                pf[k4][1] = __float_as_uint(Ps[rB*68 + base]);
                pf[k4][2] = __float_as_uint(Ps[rA*68 + base + 4]);
                pf[k4][3] = __float_as_uint(Ps[rB*68 + base + 4]);
            }
            #pragma unroll
            for (int n = 0; n < 8; n++) {
                #pragma unroll
                for (int k4 = 0; k4 < 4; k4++) {
                    const int krow = (kh*4 + k4)*8 + tig;
                    const uint32_t b0 = __float_as_uint(Vs[krow*72 + n*8 + gid]);
                    const uint32_t b1 = __float_as_uint(Vs[(krow+4)*72 + n*8 + gid]);
                    mma_tf32(oa[n], pf[k4][0], pf[k4][1], pf[k4][2], pf[k4][3], b0, b1);
                }
            }
        }
        __syncthreads();   // all reads of Ks/Vs done before next write phase
    }

    const float invA = 1.0f / lA, invB = 1.0f / lB;
    const size_t rowA = (size_t)((s*4 + b)*256 + qt*128 + rA);
    float* oA = o + rowA * 1024 + h*64;
    float* oB = oA + (size_t)8 * 1024;
    #pragma unroll
    for (int n = 0; n < 8; n++) {
        const int col = n*8 + 2*tig;
        *(float2*)(oA + col) = make_float2(tf32r(oa[n][0]*invA), tf32r(oa[n][1]*invA));
        *(float2*)(oB + col) = make_float2(tf32r(oa[n][2]*invB), tf32r(oa[n][3]*invB));
    }
}

// ---------------- launch --------------------------------------------------
extern "C" void kernel_launch(void* const* d_in, const int* in_sizes, int n_in,
                              void* d_out, int out_size) {
    const float* x        = (const float*)d_in[0];
    const float* lc1      = (const float*)d_in[1];
    const float* lc0      = (const float*)d_in[2];
    const int*   mask     = (const int*)d_in[3];
    const float* ln_x_w   = (const float*)d_in[4];
    const float* ln_x_b   = (const float*)d_in[5];
    const float* ln_l_w   = (const float*)d_in[6];
    const float* ln_l_b   = (const float*)d_in[7];
    const float* gamma_q  = (const float*)d_in[8];
    const float* gamma_k  = (const float*)d_in[9];
    const float* Wq       = (const float*)d_in[10];
    const float* Wkv      = (const float*)d_in[11];
    const float* Wout     = (const float*)d_in[12];
    const float* bout     = (const float*)d_in[13];
    float* out = (float*)d_out;

    float *xn, *lnq, *kvb, *qb, *ob, *wp;
    cudaGetSymbolAddress((void**)&xn,  g_xn);
    cudaGetSymbolAddress((void**)&lnq, g_ln);
    cudaGetSymbolAddress((void**)&kvb, g_kv);
    cudaGetSymbolAddress((void**)&qb,  g_q);
    cudaGetSymbolAddress((void**)&ob,  g_o);
    cudaGetSymbolAddress((void**)&wp,  g_wp);
    float* WkvP  = wp;
    float* WqP   = wp + (size_t)2*1024*1024;
    float* WoutP = wp + (size_t)3*1024*1024;

    cudaFuncSetAttribute(attn_kernel, cudaFuncAttributeMaxDynamicSharedMemorySize, ATTN_SMEM);
    cudaFuncSetAttribute(gemm_cp, cudaFuncAttributeMaxDynamicSharedMemorySize, GEMM_SMEM);
    cudaFuncSetAttribute(gemm_fused, cudaFuncAttributeMaxDynamicSharedMemorySize, GEMM_SMEM);

    // 0) LN(x)
    ln_kernel<<<B_ * N_, 256>>>(x, xn, ln_x_w, ln_x_b);
    // 1) pack all three weights
    pack_all<<<dim3(16, 32, 3), 256>>>(Wkv, Wq, Wout, wp);
    // 2) LN(latents) both streams
    ln_lat_kernel<<<dim3(B_ * M_, 2), 256>>>(lc1, lc0, lnq, ln_l_w, ln_l_b);
    // 3) fused kv + q GEMM — PROFILED LAUNCH
    gemm_fused<<<dim3(16, 80), 256, GEMM_SMEM>>>(xn, WkvP, kvb, lnq, WqP, qb);
    // 4) fused flash attention (both streams), rmsnorms folded, K/V prefetch
    attn_kernel<<<dim3(2, HEADS_, 2 * B_), 256, ATTN_SMEM>>>(qb, kvb, mask, gamma_q, gamma_k, ob);
    // 5) out = o @ Wout + bout
    gemm_cp<<<dim3(1024/128, 2048/128), 256, GEMM_SMEM>>>(ob, WoutP, out, bout, 1024, 1024);
}